// round 1
// baseline (speedup 1.0000x reference)
#include <cuda_runtime.h>
#include <cstdint>

// TPAsyncDense: y[d] = sum_i x_i @ W[d,i] + b[d]
// x: [4][2][4096][512] f32  -> A view: [M=8192][K=2048], K split in 4 shard blocks
//    A[m][c] = x[i= c>>9][m][k= c&511]  at  i*4194304 + m*512 + k
// W: [4][4][512][2048] f32  -> B_d view: [K=2048][N=2048] row-major at d*4194304
// b: [4][2048]
// out: [4][8192][2048]
//
// Tiled fp32 SIMT GEMM using packed fma.rn.f32x2 (FFMA2) accumulators:
// sm_103a plain FFMA is half-rate (rt_SMSP=2); f32x2 recovers 128 FMA/cyc/SM.

#define BM 128
#define BN 128
#define BK 16
#define KT 128           // 2048 / BK
#define SHARD_STRIDE 4194304  // 8192*512
#define PADM 130         // BM + 2 pad -> conflict-free transposed STS

#define FMA2(d, a, b) asm("fma.rn.f32x2 %0, %1, %2, %0;" : "+l"(d) : "l"(a), "l"(b))
#define PACK_DUP(d, s) asm("mov.b64 %0, {%1, %1};" : "=l"(d) : "r"(__float_as_uint(s)))

__device__ __forceinline__ float lo32(unsigned long long p) {
    return __uint_as_float((unsigned)p);
}
__device__ __forceinline__ float hi32(unsigned long long p) {
    return __uint_as_float((unsigned)(p >> 32));
}

__global__ __launch_bounds__(256, 2)
void tp_dense_kernel(const float* __restrict__ x,
                     const float* __restrict__ W,
                     const float* __restrict__ bias,
                     float* __restrict__ out)
{
    const int d  = blockIdx.z;
    const int mB = blockIdx.y * BM;
    const int nB = blockIdx.x * BN;

    const float* __restrict__ Wd = W + (size_t)d * 2048 * 2048;

    __shared__ __align__(16) float As[2][BK][PADM];
    __shared__ __align__(16) float Bs[2][BK][BN];

    const int tid = threadIdx.x;

    // A load mapping: idx in [0,512): row = idx>>2 (0..127), kc = (idx&3)*4
    const int aRow0 = tid >> 2;
    const int aKc   = (tid & 3) * 4;
    // B load mapping: idx in [0,512): row = idx>>5 (0..15), nc = (idx&31)*4
    const int bRow0 = tid >> 5;
    const int bNc   = (tid & 31) * 4;

    // compute mapping: 16x16 thread grid, 8x8 outputs each
    const int ty = tid >> 4;
    const int tx = tid & 15;
    const int rowBase = ty * 8;
    const int colBase = tx * 8;

    unsigned long long acc[4][8];
#pragma unroll
    for (int m2 = 0; m2 < 4; m2++)
#pragma unroll
        for (int n = 0; n < 8; n++)
            acc[m2][n] = 0ULL;

    float4 ar0, ar1, br0, br1;

    // ---- prologue: load chunk 0 ----
    {
        const int kk = 0;
        const int shard = kk >> 9;
        const int kloc  = kk & 511;
        const float* ab = x + (size_t)shard * SHARD_STRIDE + kloc;
        ar0 = *reinterpret_cast<const float4*>(ab + (size_t)(mB + aRow0)       * 512 + aKc);
        ar1 = *reinterpret_cast<const float4*>(ab + (size_t)(mB + aRow0 + 64)  * 512 + aKc);
        br0 = *reinterpret_cast<const float4*>(Wd + (size_t)(kk + bRow0)      * 2048 + nB + bNc);
        br1 = *reinterpret_cast<const float4*>(Wd + (size_t)(kk + bRow0 + 8)  * 2048 + nB + bNc);

        As[0][aKc + 0][aRow0] = ar0.x;
        As[0][aKc + 1][aRow0] = ar0.y;
        As[0][aKc + 2][aRow0] = ar0.z;
        As[0][aKc + 3][aRow0] = ar0.w;
        As[0][aKc + 0][aRow0 + 64] = ar1.x;
        As[0][aKc + 1][aRow0 + 64] = ar1.y;
        As[0][aKc + 2][aRow0 + 64] = ar1.z;
        As[0][aKc + 3][aRow0 + 64] = ar1.w;
        *reinterpret_cast<float4*>(&Bs[0][bRow0][bNc])     = br0;
        *reinterpret_cast<float4*>(&Bs[0][bRow0 + 8][bNc]) = br1;
    }
    __syncthreads();

    for (int kt = 0; kt < KT; kt++) {
        const int cur = kt & 1;
        const int nxt = cur ^ 1;

        // prefetch next chunk into registers
        if (kt + 1 < KT) {
            const int kk = (kt + 1) * BK;
            const int shard = kk >> 9;
            const int kloc  = kk & 511;
            const float* ab = x + (size_t)shard * SHARD_STRIDE + kloc;
            ar0 = *reinterpret_cast<const float4*>(ab + (size_t)(mB + aRow0)      * 512 + aKc);
            ar1 = *reinterpret_cast<const float4*>(ab + (size_t)(mB + aRow0 + 64) * 512 + aKc);
            br0 = *reinterpret_cast<const float4*>(Wd + (size_t)(kk + bRow0)     * 2048 + nB + bNc);
            br1 = *reinterpret_cast<const float4*>(Wd + (size_t)(kk + bRow0 + 8) * 2048 + nB + bNc);
        }

        // compute on current buffer
#pragma unroll
        for (int k = 0; k < BK; k++) {
            const unsigned long long* Ap =
                reinterpret_cast<const unsigned long long*>(&As[cur][k][rowBase]);
            unsigned long long aa0 = Ap[0];
            unsigned long long aa1 = Ap[1];
            unsigned long long aa2 = Ap[2];
            unsigned long long aa3 = Ap[3];

            float4 bv0 = *reinterpret_cast<const float4*>(&Bs[cur][k][colBase]);
            float4 bv1 = *reinterpret_cast<const float4*>(&Bs[cur][k][colBase + 4]);

            unsigned long long bb[8];
            PACK_DUP(bb[0], bv0.x);
            PACK_DUP(bb[1], bv0.y);
            PACK_DUP(bb[2], bv0.z);
            PACK_DUP(bb[3], bv0.w);
            PACK_DUP(bb[4], bv1.x);
            PACK_DUP(bb[5], bv1.y);
            PACK_DUP(bb[6], bv1.z);
            PACK_DUP(bb[7], bv1.w);

#pragma unroll
            for (int n = 0; n < 8; n++) {
                FMA2(acc[0][n], aa0, bb[n]);
                FMA2(acc[1][n], aa1, bb[n]);
                FMA2(acc[2][n], aa2, bb[n]);
                FMA2(acc[3][n], aa3, bb[n]);
            }
        }

        // stage next chunk into the other buffer
        if (kt + 1 < KT) {
            As[nxt][aKc + 0][aRow0] = ar0.x;
            As[nxt][aKc + 1][aRow0] = ar0.y;
            As[nxt][aKc + 2][aRow0] = ar0.z;
            As[nxt][aKc + 3][aRow0] = ar0.w;
            As[nxt][aKc + 0][aRow0 + 64] = ar1.x;
            As[nxt][aKc + 1][aRow0 + 64] = ar1.y;
            As[nxt][aKc + 2][aRow0 + 64] = ar1.z;
            As[nxt][aKc + 3][aRow0 + 64] = ar1.w;
            *reinterpret_cast<float4*>(&Bs[nxt][bRow0][bNc])     = br0;
            *reinterpret_cast<float4*>(&Bs[nxt][bRow0 + 8][bNc]) = br1;
            __syncthreads();
        }
    }

    // ---- epilogue: bias + store ----
    const float* bd = bias + d * 2048 + nB + colBase;
    const float4 bvlo = *reinterpret_cast<const float4*>(bd);
    const float4 bvhi = *reinterpret_cast<const float4*>(bd + 4);

    float* obase = out + ((size_t)d * 8192 + mB + rowBase) * 2048 + nB + colBase;

#pragma unroll
    for (int m2 = 0; m2 < 4; m2++) {
        float4 e0, e1, o0, o1;  // even row (lo lanes), odd row (hi lanes)
        e0.x = lo32(acc[m2][0]) + bvlo.x;
        e0.y = lo32(acc[m2][1]) + bvlo.y;
        e0.z = lo32(acc[m2][2]) + bvlo.z;
        e0.w = lo32(acc[m2][3]) + bvlo.w;
        e1.x = lo32(acc[m2][4]) + bvhi.x;
        e1.y = lo32(acc[m2][5]) + bvhi.y;
        e1.z = lo32(acc[m2][6]) + bvhi.z;
        e1.w = lo32(acc[m2][7]) + bvhi.w;
        o0.x = hi32(acc[m2][0]) + bvlo.x;
        o0.y = hi32(acc[m2][1]) + bvlo.y;
        o0.z = hi32(acc[m2][2]) + bvlo.z;
        o0.w = hi32(acc[m2][3]) + bvlo.w;
        o1.x = hi32(acc[m2][4]) + bvhi.x;
        o1.y = hi32(acc[m2][5]) + bvhi.y;
        o1.z = hi32(acc[m2][6]) + bvhi.z;
        o1.w = hi32(acc[m2][7]) + bvhi.w;

        float* r0 = obase + (size_t)(2 * m2)     * 2048;
        float* r1 = obase + (size_t)(2 * m2 + 1) * 2048;
        *reinterpret_cast<float4*>(r0)     = e0;
        *reinterpret_cast<float4*>(r0 + 4) = e1;
        *reinterpret_cast<float4*>(r1)     = o0;
        *reinterpret_cast<float4*>(r1 + 4) = o1;
    }
}

extern "C" void kernel_launch(void* const* d_in, const int* in_sizes, int n_in,
                              void* d_out, int out_size)
{
    const float* x    = (const float*)d_in[0];
    const float* W    = (const float*)d_in[1];
    const float* bias = (const float*)d_in[2];
    float* out        = (float*)d_out;

    dim3 grid(2048 / BN, 8192 / BM, 4);  // (16, 64, 4)
    tp_dense_kernel<<<grid, 256>>>(x, W, bias, out);
}

// round 3
// speedup vs baseline: 8.2349x; 8.2349x over previous
#include <cuda_runtime.h>
#include <cuda.h>
#include <cuda_bf16.h>
#include <cstdint>

// ---------------------------------------------------------------------------
// TPAsyncDense on tcgen05:
//   y[d] = sum_i x_i @ W[d,i] + b[d]
//   A view: [M=8192, K=2048] fp32 (x, K sharded by i)
//   B view per d: [K=2048, N=2048] fp32 (W[d])
// 2-term bf16 split: v = hi + lo. 3-term product via concatenated K' = 6144:
//   segments: seg0 Ah*Bh, seg1 Al*Bh, seg2 Ah*Bl   (fp32 accumulate in TMEM)
//
// tcgen05 is arch-SPECIFIC: only compiled in the sm_103a/compute_103a pass.
// The plain compute_103 PTX pass gets an empty stub (never executed on GB300).
// ---------------------------------------------------------------------------

#if defined(__CUDA_ARCH_FEAT_SM103_ALL) || defined(__CUDA_ARCH_FEAT_SM100_ALL) || \
    defined(__CUDA_ARCH_SPECIFIC__) || defined(__CUDA_ARCH_FAMILY_SPECIFIC__)
#define TC_OK 1
#else
#define TC_OK 0
#endif

#define M_TOT 8192
#define N_TOT 2048
#define K_TOT 2048
#define D_TOT 4

#define BM 128
#define BN 256
#define KB 64            // K elements per chunk (128 bytes bf16 = SW128 row)
#define STAGES 4
#define CHUNKS_PER_SEG (K_TOT / KB)   // 32
#define NCHUNK (3 * CHUNKS_PER_SEG)   // 96

// SMEM layout (dynamic)
#define OFF_TMEM   0
#define OFF_FULL   16                 // 4 x 8B
#define OFF_EMPTY  48                 // 4 x 8B
#define OFF_DONE   80
#define A_BYTES    (BM * 128)         // 16384 per stage
#define B_BYTES    (BN * 128)         // 32768 per stage
#define OFF_A      1024
#define OFF_B      (OFF_A + STAGES * A_BYTES)          // 66560
#define SMEM_TOTAL (OFF_B + STAGES * B_BYTES)          // 197632

#define CHUNK_TX   (A_BYTES + B_BYTES)                 // 49152

// idesc kind::f16: dtype=F32(1<<4), atype=BF16(1<<7), btype=BF16(1<<10),
// N=128 -> (128/8)<<17, M=128 -> (128/16)<<24
#define IDESC_N128 ((1u<<4) | (1u<<7) | (1u<<10) | (16u<<17) | (8u<<24))

// SW128 K-major smem descriptor base (LBO=1, SBO=64, version=1, layout=2)
static constexpr uint64_t DESC_BASE_SW128 =
    (uint64_t(2) << 61) | (uint64_t(1) << 46) | (uint64_t(64) << 32) | (uint64_t(1) << 16);

// ------------------------- scratch (static device mem) ---------------------
__device__ __align__(1024) __nv_bfloat16 g_Ah[(size_t)M_TOT * K_TOT];
__device__ __align__(1024) __nv_bfloat16 g_Al[(size_t)M_TOT * K_TOT];
__device__ __align__(1024) __nv_bfloat16 g_Bh[(size_t)D_TOT * N_TOT * K_TOT];
__device__ __align__(1024) __nv_bfloat16 g_Bl[(size_t)D_TOT * N_TOT * K_TOT];

// ------------------------------ PTX helpers --------------------------------
__device__ __forceinline__ uint32_t smem_u32(const void* p) {
    uint32_t a;
    asm("{ .reg .u64 t; cvta.to.shared.u64 t, %1; cvt.u32.u64 %0, t; }" : "=r"(a) : "l"(p));
    return a;
}
__device__ __forceinline__ uint32_t elect_one() {
    uint32_t pred;
    asm volatile("{\n\t.reg .pred p;\n\telect.sync _|p, 0xFFFFFFFF;\n\tselp.b32 %0, 1, 0, p;\n\t}"
                 : "=r"(pred));
    return pred;
}
#define MBAR_INIT(addr, cnt) \
    asm volatile("mbarrier.init.shared.b64 [%0], %1;" :: "r"(addr), "r"(cnt) : "memory")
#define MBAR_INVAL(addr) \
    asm volatile("mbarrier.inval.shared.b64 [%0];" :: "r"(addr) : "memory")
#define MBAR_EXPECT_TX(addr, bytes) \
    asm volatile("mbarrier.arrive.expect_tx.shared.b64 _, [%0], %1;" :: "r"(addr), "r"(bytes) : "memory")

__device__ __forceinline__ void mbar_wait_acq(uint32_t mbar, uint32_t parity) {
    asm volatile(
        "{\n\t.reg .pred P1;\n\t"
        "WAIT_LOOP_%=:\n\t"
        "mbarrier.try_wait.parity.acquire.cta.shared::cta.b64 P1, [%0], %1, 0x989680;\n\t"
        "@P1 bra.uni WAIT_DONE_%=;\n\t"
        "bra.uni WAIT_LOOP_%=;\n\t"
        "WAIT_DONE_%=:\n\t}"
        :: "r"(mbar), "r"(parity) : "memory");
}
__device__ __forceinline__ void mbar_wait_rel(uint32_t mbar, uint32_t parity) {
    asm volatile(
        "{\n\t.reg .pred P1;\n\t"
        "WAIT_LOOP_%=:\n\t"
        "mbarrier.try_wait.parity.relaxed.cta.shared::cta.b64 P1, [%0], %1, 0x989680;\n\t"
        "@P1 bra.uni WAIT_DONE_%=;\n\t"
        "bra.uni WAIT_LOOP_%=;\n\t"
        "WAIT_DONE_%=:\n\t}"
        :: "r"(mbar), "r"(parity) : "memory");
}

__device__ __forceinline__ void tma_load_3d(uint32_t smem_dst, const CUtensorMap* map,
                                            int cx, int cy, int cz, uint32_t mbar) {
    asm volatile(
        "cp.async.bulk.tensor.3d.shared::cta.global.tile.mbarrier::complete_tx::bytes "
        "[%0], [%1, {%2, %3, %4}], [%5];"
        :: "r"(smem_dst), "l"(map), "r"(cx), "r"(cy), "r"(cz), "r"(mbar) : "memory");
}

#if TC_OK
__device__ __forceinline__ void mma_f16_ss(uint32_t dtm, uint64_t adesc, uint64_t bdesc,
                                           uint32_t idesc, uint32_t en) {
    asm volatile(
        "{\n\t.reg .pred p;\n\tsetp.ne.u32 p, %5, 0;\n\t"
        "tcgen05.mma.cta_group::1.kind::f16 [%0], %1, %2, %3, {%4, %4, %4, %4}, p;\n\t}"
        :: "r"(dtm), "l"(adesc), "l"(bdesc), "r"(idesc), "r"(0u), "r"(en) : "memory");
}

#define TC_ALLOC(smem_addr, cols) \
    asm volatile("tcgen05.alloc.cta_group::1.sync.aligned.shared::cta.b32 [%0], %1;" \
                 :: "r"(smem_addr), "r"(cols) : "memory")
#define TC_DEALLOC(tmem, cols) \
    asm volatile("tcgen05.dealloc.cta_group::1.sync.aligned.b32 %0, %1;" :: "r"(tmem), "r"(cols))
#define TC_RELINQ() \
    asm volatile("tcgen05.relinquish_alloc_permit.cta_group::1.sync.aligned;")
#define TC_COMMIT(mbar) \
    asm volatile("tcgen05.commit.cta_group::1.mbarrier::arrive::one.shared::cluster.b64 [%0];" \
                 :: "r"(mbar) : "memory")
#define TC_FENCE_AFTER() asm volatile("tcgen05.fence::after_thread_sync;" ::: "memory")
#define TC_FENCE_BEFORE() asm volatile("tcgen05.fence::before_thread_sync;" ::: "memory")
#define TC_WAIT_LD() asm volatile("tcgen05.wait::ld.sync.aligned;" ::: "memory")

#define TC_LD_X32(r, tm) \
    asm volatile( \
        "tcgen05.ld.sync.aligned.32x32b.x32.b32 " \
        "{%0, %1, %2, %3, %4, %5, %6, %7, " \
        " %8, %9, %10, %11, %12, %13, %14, %15, " \
        " %16, %17, %18, %19, %20, %21, %22, %23, " \
        " %24, %25, %26, %27, %28, %29, %30, %31}, [%32];" \
        : "=r"((r)[0]),  "=r"((r)[1]),  "=r"((r)[2]),  "=r"((r)[3]), \
          "=r"((r)[4]),  "=r"((r)[5]),  "=r"((r)[6]),  "=r"((r)[7]), \
          "=r"((r)[8]),  "=r"((r)[9]),  "=r"((r)[10]), "=r"((r)[11]), \
          "=r"((r)[12]), "=r"((r)[13]), "=r"((r)[14]), "=r"((r)[15]), \
          "=r"((r)[16]), "=r"((r)[17]), "=r"((r)[18]), "=r"((r)[19]), \
          "=r"((r)[20]), "=r"((r)[21]), "=r"((r)[22]), "=r"((r)[23]), \
          "=r"((r)[24]), "=r"((r)[25]), "=r"((r)[26]), "=r"((r)[27]), \
          "=r"((r)[28]), "=r"((r)[29]), "=r"((r)[30]), "=r"((r)[31]) \
        : "r"(tm))
#endif // TC_OK

// ------------------------------ prep kernels -------------------------------
__device__ __forceinline__ void split1(float v, unsigned short& h, unsigned short& l) {
    __nv_bfloat16 hb = __float2bfloat16_rn(v);
    float r = v - __bfloat162float(hb);
    __nv_bfloat16 lb = __float2bfloat16_rn(r);
    h = *reinterpret_cast<unsigned short*>(&hb);
    l = *reinterpret_cast<unsigned short*>(&lb);
}

// x: [4][8192][512] f32 -> Ah/Al: [8192][2048] bf16 (K = shard*512 + k)
__global__ void split_x_kernel(const float* __restrict__ x,
                               __nv_bfloat16* __restrict__ Ah,
                               __nv_bfloat16* __restrict__ Al) {
    size_t t = (size_t)blockIdx.x * blockDim.x + threadIdx.x;
    size_t e = t * 4;
    int i = (int)(e >> 22);
    int m = (int)((e >> 9) & 8191);
    int k = (int)(e & 511);
    float4 v = reinterpret_cast<const float4*>(x)[t];
    size_t o = (size_t)m * 2048 + i * 512 + k;
    ushort4 h, l;
    split1(v.x, h.x, l.x);
    split1(v.y, h.y, l.y);
    split1(v.z, h.z, l.z);
    split1(v.w, h.w, l.w);
    *reinterpret_cast<ushort4*>(Ah + o) = h;
    *reinterpret_cast<ushort4*>(Al + o) = l;
}

// W: [4][4][512][2048] (d,i,k,n) -> Bh/Bl: [4][2048(n)][2048(kg)] bf16 (transpose)
__global__ void split_w_kernel(const float* __restrict__ W,
                               __nv_bfloat16* __restrict__ Bh,
                               __nv_bfloat16* __restrict__ Bl) {
    __shared__ float tile[32][33];
    int di = blockIdx.z;
    int d = di >> 2, i = di & 3;
    int k0 = blockIdx.y * 32, n0 = blockIdx.x * 32;
    int tx = threadIdx.x, ty = threadIdx.y;   // 32 x 8
    const float* Wdi = W + (size_t)di * 512 * 2048;
#pragma unroll
    for (int j = 0; j < 32; j += 8)
        tile[ty + j][tx] = Wdi[(size_t)(k0 + ty + j) * 2048 + n0 + tx];
    __syncthreads();
    size_t obase = (size_t)d * 2048 * 2048;
#pragma unroll
    for (int j = 0; j < 32; j += 8) {
        float v = tile[tx][ty + j];
        unsigned short h, l;
        split1(v, h, l);
        size_t o = obase + (size_t)(n0 + ty + j) * 2048 + i * 512 + k0 + tx;
        *reinterpret_cast<unsigned short*>(Bh + o) = h;
        *reinterpret_cast<unsigned short*>(Bl + o) = l;
    }
}

// ------------------------------ GEMM kernel --------------------------------
__global__ __launch_bounds__(128, 1)
void tp_gemm_kernel(const __grid_constant__ CUtensorMap tmAh,
                    const __grid_constant__ CUtensorMap tmAl,
                    const __grid_constant__ CUtensorMap tmBh,
                    const __grid_constant__ CUtensorMap tmBl,
                    const float* __restrict__ bias,
                    float* __restrict__ out) {
#if TC_OK
    extern __shared__ char smem[];
    const uint32_t sb = smem_u32(smem);
    const int tid = threadIdx.x;
    const int wid = tid >> 5;
    const int lid = tid & 31;

    const int d = blockIdx.z;
    const int mB = blockIdx.y * BM;
    const int nB = blockIdx.x * BN;

    if (wid == 0) {
        TC_ALLOC(sb + OFF_TMEM, 256);
        TC_RELINQ();
    }
    if (tid == 0) {
#pragma unroll
        for (int s = 0; s < STAGES; s++) {
            MBAR_INIT(sb + OFF_FULL + 8 * s, 1);
            MBAR_INIT(sb + OFF_EMPTY + 8 * s, 1);
        }
        MBAR_INIT(sb + OFF_DONE, 1);
    }
    __syncthreads();

    uint32_t tmem;
    asm volatile("ld.shared.b32 %0, [%1];" : "=r"(tmem) : "r"(sb + OFF_TMEM));

    if (wid == 0) {
        // -------- producer: TMA loads --------
        for (int c = 0; c < NCHUNK; c++) {
            const int s = c & (STAGES - 1);
            const int ph = (c >> 2) & 1;
            mbar_wait_rel(sb + OFF_EMPTY + 8 * s, ph ^ 1);
            if (elect_one()) {
                MBAR_EXPECT_TX(sb + OFF_FULL + 8 * s, CHUNK_TX);
                const int seg = c >> 5;             // 0,1,2
                const int kc = (c & 31) * KB;
                const CUtensorMap* ma = (seg == 1) ? &tmAl : &tmAh;
                const CUtensorMap* mb = (seg == 2) ? &tmBl : &tmBh;
                tma_load_3d(sb + OFF_A + s * A_BYTES, ma, kc, mB, 0, sb + OFF_FULL + 8 * s);
                tma_load_3d(sb + OFF_B + s * B_BYTES, mb, kc, nB, d, sb + OFF_FULL + 8 * s);
            }
        }
    } else if (wid == 1) {
        // -------- consumer: MMA issue --------
        for (int c = 0; c < NCHUNK; c++) {
            const int s = c & (STAGES - 1);
            const int ph = (c >> 2) & 1;
            mbar_wait_acq(sb + OFF_FULL + 8 * s, ph);
            if (elect_one()) {
                const uint64_t ad = DESC_BASE_SW128 |
                    ((uint64_t)((sb + OFF_A + s * A_BYTES) >> 4) & 0x3FFF);
                const uint64_t bd0 = DESC_BASE_SW128 |
                    ((uint64_t)((sb + OFF_B + s * B_BYTES) >> 4) & 0x3FFF);
                const uint64_t bd1 = DESC_BASE_SW128 |
                    ((uint64_t)((sb + OFF_B + s * B_BYTES + 16384) >> 4) & 0x3FFF);
#pragma unroll
                for (int k4 = 0; k4 < 4; k4++) {
                    const uint32_t en = (c != 0 || k4 != 0) ? 1u : 0u;
                    mma_f16_ss(tmem,       ad + 2 * k4, bd0 + 2 * k4, IDESC_N128, en);
                    mma_f16_ss(tmem + 128, ad + 2 * k4, bd1 + 2 * k4, IDESC_N128, en);
                }
                if (c == NCHUNK - 1)
                    TC_COMMIT(sb + OFF_DONE);
                else
                    TC_COMMIT(sb + OFF_EMPTY + 8 * s);
            }
        }
    }

    // -------- epilogue: TMEM -> bias add -> GMEM --------
    mbar_wait_acq(sb + OFF_DONE, 0);
    TC_FENCE_AFTER();

    const int mRow = mB + wid * 32 + lid;
    float* orow = out + ((size_t)d * M_TOT + mRow) * N_TOT + nB;
    const float* brow = bias + d * N_TOT + nB;

#pragma unroll
    for (int nb = 0; nb < BN; nb += 32) {
        uint32_t r[32];
        TC_LD_X32(r, tmem + nb);
        TC_WAIT_LD();
#pragma unroll
        for (int j = 0; j < 32; j += 4) {
            float4 v;
            v.x = __uint_as_float(r[j + 0]) + brow[nb + j + 0];
            v.y = __uint_as_float(r[j + 1]) + brow[nb + j + 1];
            v.z = __uint_as_float(r[j + 2]) + brow[nb + j + 2];
            v.w = __uint_as_float(r[j + 3]) + brow[nb + j + 3];
            *reinterpret_cast<float4*>(orow + nb + j) = v;
        }
    }
    TC_FENCE_BEFORE();
    __syncthreads();

    if (tid == 0) {
#pragma unroll
        for (int s = 0; s < STAGES; s++) {
            MBAR_INVAL(sb + OFF_FULL + 8 * s);
            MBAR_INVAL(sb + OFF_EMPTY + 8 * s);
        }
        MBAR_INVAL(sb + OFF_DONE);
    }
    __syncthreads();
    if (wid == 0) {
        TC_DEALLOC(tmem, 256);
    }
#endif // TC_OK
}

// ------------------------------ host launch --------------------------------
typedef CUresult (*PFN_encodeTiled)(CUtensorMap*, CUtensorMapDataType, cuuint32_t, void*,
                                    const cuuint64_t*, const cuuint64_t*, const cuuint32_t*,
                                    const cuuint32_t*, CUtensorMapInterleave, CUtensorMapSwizzle,
                                    CUtensorMapL2promotion, CUtensorMapFloatOOBfill);

static void make_map_bf16(PFN_encodeTiled enc, CUtensorMap* m, void* p,
                          uint64_t d0, uint64_t d1, uint64_t d2,
                          uint64_t s1b, uint64_t s2b, uint32_t b0, uint32_t b1) {
    cuuint64_t dims[3] = {d0, d1, d2};
    cuuint64_t strides[2] = {s1b, s2b};
    cuuint32_t box[3] = {b0, b1, 1};
    cuuint32_t es[3] = {1, 1, 1};
    enc(m, CU_TENSOR_MAP_DATA_TYPE_BFLOAT16, 3, p, dims, strides, box, es,
        CU_TENSOR_MAP_INTERLEAVE_NONE, CU_TENSOR_MAP_SWIZZLE_128B,
        CU_TENSOR_MAP_L2_PROMOTION_L2_128B, CU_TENSOR_MAP_FLOAT_OOB_FILL_NONE);
}

extern "C" void kernel_launch(void* const* d_in, const int* in_sizes, int n_in,
                              void* d_out, int out_size) {
    const float* x    = (const float*)d_in[0];
    const float* W    = (const float*)d_in[1];
    const float* bias = (const float*)d_in[2];
    float* out        = (float*)d_out;

    void *pAh, *pAl, *pBh, *pBl;
    cudaGetSymbolAddress(&pAh, g_Ah);
    cudaGetSymbolAddress(&pAl, g_Al);
    cudaGetSymbolAddress(&pBh, g_Bh);
    cudaGetSymbolAddress(&pBl, g_Bl);

    void* fp = nullptr;
    cudaDriverEntryPointQueryResult qr;
    cudaGetDriverEntryPoint("cuTensorMapEncodeTiled", &fp, cudaEnableDefault, &qr);
    PFN_encodeTiled enc = (PFN_encodeTiled)fp;

    CUtensorMap mAh, mAl, mBh, mBl;
    // A: [M=8192 rows, K=2048 cols] bf16; dims {K, M, 1}; box {64, 128}
    make_map_bf16(enc, &mAh, pAh, K_TOT, M_TOT, 1,
                  (uint64_t)K_TOT * 2, (uint64_t)M_TOT * K_TOT * 2, KB, BM);
    make_map_bf16(enc, &mAl, pAl, K_TOT, M_TOT, 1,
                  (uint64_t)K_TOT * 2, (uint64_t)M_TOT * K_TOT * 2, KB, BM);
    // B: [D][N=2048 rows][K=2048 cols] bf16; dims {K, N, D}; box {64, 256}
    make_map_bf16(enc, &mBh, pBh, K_TOT, N_TOT, D_TOT,
                  (uint64_t)K_TOT * 2, (uint64_t)N_TOT * K_TOT * 2, KB, BN);
    make_map_bf16(enc, &mBl, pBl, K_TOT, N_TOT, D_TOT,
                  (uint64_t)K_TOT * 2, (uint64_t)N_TOT * K_TOT * 2, KB, BN);

    // prep: split + transpose
    split_x_kernel<<<(D_TOT * M_TOT * 512 / 4) / 256, 256>>>(
        x, (__nv_bfloat16*)pAh, (__nv_bfloat16*)pAl);
    split_w_kernel<<<dim3(2048 / 32, 512 / 32, 16), dim3(32, 8)>>>(
        W, (__nv_bfloat16*)pBh, (__nv_bfloat16*)pBl);

    cudaFuncSetAttribute(tp_gemm_kernel, cudaFuncAttributeMaxDynamicSharedMemorySize,
                         SMEM_TOTAL);
    dim3 grid(N_TOT / BN, M_TOT / BM, D_TOT);   // (8, 64, 4)
    tp_gemm_kernel<<<grid, 128, SMEM_TOTAL>>>(mAh, mAl, mBh, mBl, bias, out);
}

// round 6
// speedup vs baseline: 9.5047x; 1.1542x over previous
#include <cuda_runtime.h>
#include <cuda.h>
#include <cuda_bf16.h>
#include <cstdint>

// ---------------------------------------------------------------------------
// TPAsyncDense on tcgen05, persistent-CTA version:
//   y[d] = sum_i x_i @ W[d,i] + b[d]
// 2-term bf16 split (v = hi + lo), 3-term product per K-chunk, FUSED:
//   per 64-wide K chunk load {Ah, Al, Bh, Bl} once, issue
//   seg0 Ah*Bh, seg1 Al*Bh, seg2 Ah*Bl into the same fp32 TMEM accumulator.
// Persistent CTAs (grid = #SMs), 2-stage 96KB TMA pipeline, TMEM 2x256-col
// ping-pong so the epilogue of tile t overlaps the mainloop of tile t+1.
//
// FIX vs previous round: epilogue warps are wid 2..5; a warp's TMEM access
// goes through subpartition (wid & 3), so the output-row group must be
// (wid & 3) * 32, NOT (wid - 2) * 32.
// ---------------------------------------------------------------------------

#if defined(__CUDA_ARCH_FEAT_SM103_ALL) || defined(__CUDA_ARCH_FEAT_SM100_ALL) || \
    defined(__CUDA_ARCH_SPECIFIC__) || defined(__CUDA_ARCH_FAMILY_SPECIFIC__)
#define TC_OK 1
#else
#define TC_OK 0
#endif

#define M_TOT 8192
#define N_TOT 2048
#define K_TOT 2048
#define D_TOT 4

#define BM 128
#define BN 256
#define KB 64                      // K elems per chunk (128B bf16 = SW128 row)
#define NCHUNK 32                  // 2048 / 64
#define NTILES (D_TOT * (M_TOT / BM) * (N_TOT / BN))   // 2048

// SMEM: header (barriers) + 2 stages x {Ah 16K, Al 16K, Bh 32K, Bl 32K}
#define OFF_TMEM     0
#define OFF_FULL     16            // 2 x 8B
#define OFF_EMPTY    32            // 2 x 8B
#define OFF_ACCDONE  48            // 2 x 8B
#define OFF_ACCFREE  64            // 2 x 8B
#define A_BYTES      (BM * 128)    // 16384
#define B_BYTES      (BN * 128)    // 32768
#define STG_BYTES    (2 * A_BYTES + 2 * B_BYTES)   // 98304
#define OFF_STG      1024
#define SMEM_TOTAL   (OFF_STG + 2 * STG_BYTES)     // 197632
#define CHUNK_TX     STG_BYTES

// within a stage
#define SO_AH 0
#define SO_AL A_BYTES
#define SO_BH (2 * A_BYTES)
#define SO_BL (2 * A_BYTES + B_BYTES)

// idesc kind::f16: dtype=F32(1<<4), atype=BF16(1<<7), btype=BF16(1<<10),
// N=128 -> (128/8)<<17, M=128 -> (128/16)<<24
#define IDESC_N128 ((1u<<4) | (1u<<7) | (1u<<10) | (16u<<17) | (8u<<24))

static constexpr uint64_t DESC_BASE_SW128 =
    (uint64_t(2) << 61) | (uint64_t(1) << 46) | (uint64_t(64) << 32) | (uint64_t(1) << 16);

// ------------------------- scratch (static device mem) ---------------------
__device__ __align__(1024) __nv_bfloat16 g_Ah[(size_t)M_TOT * K_TOT];
__device__ __align__(1024) __nv_bfloat16 g_Al[(size_t)M_TOT * K_TOT];
__device__ __align__(1024) __nv_bfloat16 g_Bh[(size_t)D_TOT * N_TOT * K_TOT];
__device__ __align__(1024) __nv_bfloat16 g_Bl[(size_t)D_TOT * N_TOT * K_TOT];

// ------------------------------ PTX helpers --------------------------------
__device__ __forceinline__ uint32_t smem_u32(const void* p) {
    uint32_t a;
    asm("{ .reg .u64 t; cvta.to.shared.u64 t, %1; cvt.u32.u64 %0, t; }" : "=r"(a) : "l"(p));
    return a;
}
__device__ __forceinline__ uint32_t elect_one() {
    uint32_t pred;
    asm volatile("{\n\t.reg .pred p;\n\telect.sync _|p, 0xFFFFFFFF;\n\tselp.b32 %0, 1, 0, p;\n\t}"
                 : "=r"(pred));
    return pred;
}
#define MBAR_INIT(addr, cnt) \
    asm volatile("mbarrier.init.shared.b64 [%0], %1;" :: "r"(addr), "r"(cnt) : "memory")
#define MBAR_INVAL(addr) \
    asm volatile("mbarrier.inval.shared.b64 [%0];" :: "r"(addr) : "memory")
#define MBAR_EXPECT_TX(addr, bytes) \
    asm volatile("mbarrier.arrive.expect_tx.shared.b64 _, [%0], %1;" :: "r"(addr), "r"(bytes) : "memory")
#define MBAR_ARRIVE(addr) \
    asm volatile("mbarrier.arrive.shared.b64 _, [%0];" :: "r"(addr) : "memory")

__device__ __forceinline__ void mbar_wait_acq(uint32_t mbar, uint32_t parity) {
    asm volatile(
        "{\n\t.reg .pred P1;\n\t"
        "WAIT_LOOP_%=:\n\t"
        "mbarrier.try_wait.parity.acquire.cta.shared::cta.b64 P1, [%0], %1, 0x989680;\n\t"
        "@P1 bra.uni WAIT_DONE_%=;\n\t"
        "bra.uni WAIT_LOOP_%=;\n\t"
        "WAIT_DONE_%=:\n\t}"
        :: "r"(mbar), "r"(parity) : "memory");
}
__device__ __forceinline__ void mbar_wait_rel(uint32_t mbar, uint32_t parity) {
    asm volatile(
        "{\n\t.reg .pred P1;\n\t"
        "WAIT_LOOP_%=:\n\t"
        "mbarrier.try_wait.parity.relaxed.cta.shared::cta.b64 P1, [%0], %1, 0x989680;\n\t"
        "@P1 bra.uni WAIT_DONE_%=;\n\t"
        "bra.uni WAIT_LOOP_%=;\n\t"
        "WAIT_DONE_%=:\n\t}"
        :: "r"(mbar), "r"(parity) : "memory");
}

__device__ __forceinline__ void tma_load_3d(uint32_t smem_dst, const CUtensorMap* map,
                                            int cx, int cy, int cz, uint32_t mbar) {
    asm volatile(
        "cp.async.bulk.tensor.3d.shared::cta.global.tile.mbarrier::complete_tx::bytes "
        "[%0], [%1, {%2, %3, %4}], [%5];"
        :: "r"(smem_dst), "l"(map), "r"(cx), "r"(cy), "r"(cz), "r"(mbar) : "memory");
}

#if TC_OK
__device__ __forceinline__ void mma_f16_ss(uint32_t dtm, uint64_t adesc, uint64_t bdesc,
                                           uint32_t idesc, uint32_t en) {
    asm volatile(
        "{\n\t.reg .pred p;\n\tsetp.ne.u32 p, %5, 0;\n\t"
        "tcgen05.mma.cta_group::1.kind::f16 [%0], %1, %2, %3, {%4, %4, %4, %4}, p;\n\t}"
        :: "r"(dtm), "l"(adesc), "l"(bdesc), "r"(idesc), "r"(0u), "r"(en) : "memory");
}

#define TC_ALLOC(smem_addr, cols) \
    asm volatile("tcgen05.alloc.cta_group::1.sync.aligned.shared::cta.b32 [%0], %1;" \
                 :: "r"(smem_addr), "r"(cols) : "memory")
#define TC_DEALLOC(tmem, cols) \
    asm volatile("tcgen05.dealloc.cta_group::1.sync.aligned.b32 %0, %1;" :: "r"(tmem), "r"(cols))
#define TC_RELINQ() \
    asm volatile("tcgen05.relinquish_alloc_permit.cta_group::1.sync.aligned;")
#define TC_COMMIT(mbar) \
    asm volatile("tcgen05.commit.cta_group::1.mbarrier::arrive::one.shared::cluster.b64 [%0];" \
                 :: "r"(mbar) : "memory")
#define TC_FENCE_AFTER() asm volatile("tcgen05.fence::after_thread_sync;" ::: "memory")
#define TC_FENCE_BEFORE() asm volatile("tcgen05.fence::before_thread_sync;" ::: "memory")
#define TC_WAIT_LD() asm volatile("tcgen05.wait::ld.sync.aligned;" ::: "memory")

#define TC_LD_X32(r, tm) \
    asm volatile( \
        "tcgen05.ld.sync.aligned.32x32b.x32.b32 " \
        "{%0, %1, %2, %3, %4, %5, %6, %7, " \
        " %8, %9, %10, %11, %12, %13, %14, %15, " \
        " %16, %17, %18, %19, %20, %21, %22, %23, " \
        " %24, %25, %26, %27, %28, %29, %30, %31}, [%32];" \
        : "=r"((r)[0]),  "=r"((r)[1]),  "=r"((r)[2]),  "=r"((r)[3]), \
          "=r"((r)[4]),  "=r"((r)[5]),  "=r"((r)[6]),  "=r"((r)[7]), \
          "=r"((r)[8]),  "=r"((r)[9]),  "=r"((r)[10]), "=r"((r)[11]), \
          "=r"((r)[12]), "=r"((r)[13]), "=r"((r)[14]), "=r"((r)[15]), \
          "=r"((r)[16]), "=r"((r)[17]), "=r"((r)[18]), "=r"((r)[19]), \
          "=r"((r)[20]), "=r"((r)[21]), "=r"((r)[22]), "=r"((r)[23]), \
          "=r"((r)[24]), "=r"((r)[25]), "=r"((r)[26]), "=r"((r)[27]), \
          "=r"((r)[28]), "=r"((r)[29]), "=r"((r)[30]), "=r"((r)[31]) \
        : "r"(tm))
#endif // TC_OK

// ------------------------------ prep kernels -------------------------------
__device__ __forceinline__ void split1(float v, unsigned short& h, unsigned short& l) {
    __nv_bfloat16 hb = __float2bfloat16_rn(v);
    float r = v - __bfloat162float(hb);
    __nv_bfloat16 lb = __float2bfloat16_rn(r);
    h = *reinterpret_cast<unsigned short*>(&hb);
    l = *reinterpret_cast<unsigned short*>(&lb);
}

// x: [4][8192][512] f32 -> Ah/Al: [8192][2048] bf16 (K = shard*512 + k)
__global__ void split_x_kernel(const float* __restrict__ x,
                               __nv_bfloat16* __restrict__ Ah,
                               __nv_bfloat16* __restrict__ Al) {
    size_t t = (size_t)blockIdx.x * blockDim.x + threadIdx.x;
    size_t e = t * 4;
    int i = (int)(e >> 22);
    int m = (int)((e >> 9) & 8191);
    int k = (int)(e & 511);
    float4 v = reinterpret_cast<const float4*>(x)[t];
    size_t o = (size_t)m * 2048 + i * 512 + k;
    ushort4 h, l;
    split1(v.x, h.x, l.x);
    split1(v.y, h.y, l.y);
    split1(v.z, h.z, l.z);
    split1(v.w, h.w, l.w);
    *reinterpret_cast<ushort4*>(Ah + o) = h;
    *reinterpret_cast<ushort4*>(Al + o) = l;
}

// W: [4][4][512][2048] (d,i,k,n) -> Bh/Bl: [4][2048(n)][2048(kg)] bf16 (transpose)
__global__ void split_w_kernel(const float* __restrict__ W,
                               __nv_bfloat16* __restrict__ Bh,
                               __nv_bfloat16* __restrict__ Bl) {
    __shared__ float tile[32][33];
    int di = blockIdx.z;
    int d = di >> 2, i = di & 3;
    int k0 = blockIdx.y * 32, n0 = blockIdx.x * 32;
    int tx = threadIdx.x, ty = threadIdx.y;   // 32 x 8
    const float* Wdi = W + (size_t)di * 512 * 2048;
#pragma unroll
    for (int j = 0; j < 32; j += 8)
        tile[ty + j][tx] = Wdi[(size_t)(k0 + ty + j) * 2048 + n0 + tx];
    __syncthreads();
    size_t obase = (size_t)d * 2048 * 2048;
#pragma unroll
    for (int j = 0; j < 32; j += 8) {
        float v = tile[tx][ty + j];
        unsigned short h, l;
        split1(v, h, l);
        size_t o = obase + (size_t)(n0 + ty + j) * 2048 + i * 512 + k0 + tx;
        *reinterpret_cast<unsigned short*>(Bh + o) = h;
        *reinterpret_cast<unsigned short*>(Bl + o) = l;
    }
}

// ------------------------------ GEMM kernel --------------------------------
__global__ __launch_bounds__(192, 1)
void tp_gemm_kernel(const __grid_constant__ CUtensorMap tmAh,
                    const __grid_constant__ CUtensorMap tmAl,
                    const __grid_constant__ CUtensorMap tmBh,
                    const __grid_constant__ CUtensorMap tmBl,
                    const float* __restrict__ bias,
                    float* __restrict__ out,
                    int gridSz) {
#if TC_OK
    extern __shared__ char smem[];
    const uint32_t sb = smem_u32(smem);
    const int tid = threadIdx.x;
    const int wid = tid >> 5;
    const int lid = tid & 31;
    const int bid = blockIdx.x;

    if (wid == 0) {
        TC_ALLOC(sb + OFF_TMEM, 512);
        TC_RELINQ();
    }
    if (tid == 0) {
#pragma unroll
        for (int s = 0; s < 2; s++) {
            MBAR_INIT(sb + OFF_FULL + 8 * s, 1);
            MBAR_INIT(sb + OFF_EMPTY + 8 * s, 1);
            MBAR_INIT(sb + OFF_ACCDONE + 8 * s, 1);
            MBAR_INIT(sb + OFF_ACCFREE + 8 * s, 4);   // 4 epilogue warps
        }
    }
    __syncthreads();

    uint32_t tmem;
    asm volatile("ld.shared.b32 %0, [%1];" : "=r"(tmem) : "r"(sb + OFF_TMEM));

    if (wid == 0) {
        // ---------------- producer: TMA loads (fused chunk) ----------------
        uint32_t cc = 0;
        for (int t = bid; t < NTILES; t += gridSz) {
            const int nIdx = t & 7;            // n fastest
            const int mIdx = (t >> 3) & 63;
            const int d    = t >> 9;
            const int mB = mIdx * BM;
            const int nB = nIdx * BN;
            for (int chunk = 0; chunk < NCHUNK; chunk++, cc++) {
                const int s = cc & 1;
                const uint32_t ph = ((cc >> 1) & 1) ^ 1;
                mbar_wait_rel(sb + OFF_EMPTY + 8 * s, ph);
                if (elect_one()) {
                    const uint32_t fb = sb + OFF_FULL + 8 * s;
                    const uint32_t stg = sb + OFF_STG + s * STG_BYTES;
                    const int kc = chunk * KB;
                    MBAR_EXPECT_TX(fb, CHUNK_TX);
                    tma_load_3d(stg + SO_AH, &tmAh, kc, mB, 0, fb);
                    tma_load_3d(stg + SO_AL, &tmAl, kc, mB, 0, fb);
                    tma_load_3d(stg + SO_BH, &tmBh, kc, nB, d, fb);
                    tma_load_3d(stg + SO_BL, &tmBl, kc, nB, d, fb);
                }
            }
        }
    } else if (wid == 1) {
        // ---------------- consumer: MMA issue ----------------
        uint32_t cc = 0;
        uint32_t tIdx = 0;
        for (int t = bid; t < NTILES; t += gridSz, tIdx++) {
            const int b = tIdx & 1;
            // wait for epilogue to free accumulator buffer b
            mbar_wait_rel(sb + OFF_ACCFREE + 8 * b, ((tIdx >> 1) & 1) ^ 1);
            TC_FENCE_AFTER();
            const uint32_t dtm0 = tmem + b * 256;
            const uint32_t dtm1 = dtm0 + 128;
            for (int chunk = 0; chunk < NCHUNK; chunk++, cc++) {
                const int s = cc & 1;
                mbar_wait_acq(sb + OFF_FULL + 8 * s, (cc >> 1) & 1);
                if (elect_one()) {
                    const uint32_t stg = sb + OFF_STG + s * STG_BYTES;
                    const uint64_t adh = DESC_BASE_SW128 | ((uint64_t)((stg + SO_AH) >> 4) & 0x3FFF);
                    const uint64_t adl = DESC_BASE_SW128 | ((uint64_t)((stg + SO_AL) >> 4) & 0x3FFF);
                    const uint64_t bdh = DESC_BASE_SW128 | ((uint64_t)((stg + SO_BH) >> 4) & 0x3FFF);
                    const uint64_t bdl = DESC_BASE_SW128 | ((uint64_t)((stg + SO_BL) >> 4) & 0x3FFF);
#pragma unroll
                    for (int k4 = 0; k4 < 4; k4++) {
                        const uint32_t en = (chunk != 0 || k4 != 0) ? 1u : 0u;
                        mma_f16_ss(dtm0, adh + 2 * k4, bdh + 2 * k4,        IDESC_N128, en);
                        mma_f16_ss(dtm1, adh + 2 * k4, bdh + 1024 + 2 * k4, IDESC_N128, en);
                    }
#pragma unroll
                    for (int k4 = 0; k4 < 4; k4++) {
                        mma_f16_ss(dtm0, adl + 2 * k4, bdh + 2 * k4,        IDESC_N128, 1u);
                        mma_f16_ss(dtm1, adl + 2 * k4, bdh + 1024 + 2 * k4, IDESC_N128, 1u);
                    }
#pragma unroll
                    for (int k4 = 0; k4 < 4; k4++) {
                        mma_f16_ss(dtm0, adh + 2 * k4, bdl + 2 * k4,        IDESC_N128, 1u);
                        mma_f16_ss(dtm1, adh + 2 * k4, bdl + 1024 + 2 * k4, IDESC_N128, 1u);
                    }
                    TC_COMMIT(sb + OFF_EMPTY + 8 * s);
                    if (chunk == NCHUNK - 1)
                        TC_COMMIT(sb + OFF_ACCDONE + 8 * b);
                }
            }
        }
    } else {
        // ---------------- epilogue: 4 warps (wid 2..5) ----------------
        // A warp reads TMEM through subpartition (wid & 3): that determines
        // which 32 M-rows of the tile this warp holds.
        const int sp = wid & 3;                 // physical TMEM subpartition
        uint32_t tIdx = 0;
        for (int t = bid; t < NTILES; t += gridSz, tIdx++) {
            const int b = tIdx & 1;
            const int nIdx = t & 7;
            const int mIdx = (t >> 3) & 63;
            const int d    = t >> 9;
            const int mB = mIdx * BM;
            const int nB = nIdx * BN;

            mbar_wait_acq(sb + OFF_ACCDONE + 8 * b, (tIdx >> 1) & 1);
            TC_FENCE_AFTER();

            const int mRow = mB + sp * 32 + lid;
            float* orow = out + ((size_t)d * M_TOT + mRow) * N_TOT + nB;
            const float* brow = bias + d * N_TOT + nB;
            const uint32_t tbase = tmem + b * 256;

#pragma unroll
            for (int nb = 0; nb < BN; nb += 32) {
                uint32_t r[32];
                TC_LD_X32(r, tbase + nb);
                TC_WAIT_LD();
#pragma unroll
                for (int j = 0; j < 32; j += 4) {
                    const float4 bv = *reinterpret_cast<const float4*>(brow + nb + j);
                    float4 v;
                    v.x = __uint_as_float(r[j + 0]) + bv.x;
                    v.y = __uint_as_float(r[j + 1]) + bv.y;
                    v.z = __uint_as_float(r[j + 2]) + bv.z;
                    v.w = __uint_as_float(r[j + 3]) + bv.w;
                    *reinterpret_cast<float4*>(orow + nb + j) = v;
                }
            }
            TC_FENCE_BEFORE();
            if (lid == 0)
                MBAR_ARRIVE(sb + OFF_ACCFREE + 8 * b);
        }
    }

    __syncthreads();
    if (tid == 0) {
#pragma unroll
        for (int s = 0; s < 2; s++) {
            MBAR_INVAL(sb + OFF_FULL + 8 * s);
            MBAR_INVAL(sb + OFF_EMPTY + 8 * s);
            MBAR_INVAL(sb + OFF_ACCDONE + 8 * s);
            MBAR_INVAL(sb + OFF_ACCFREE + 8 * s);
        }
    }
    __syncthreads();
    if (wid == 0) {
        TC_DEALLOC(tmem, 512);
    }
#endif // TC_OK
}

// ------------------------------ host launch --------------------------------
typedef CUresult (*PFN_encodeTiled)(CUtensorMap*, CUtensorMapDataType, cuuint32_t, void*,
                                    const cuuint64_t*, const cuuint64_t*, const cuuint32_t*,
                                    const cuuint32_t*, CUtensorMapInterleave, CUtensorMapSwizzle,
                                    CUtensorMapL2promotion, CUtensorMapFloatOOBfill);

static void make_map_bf16(PFN_encodeTiled enc, CUtensorMap* m, void* p,
                          uint64_t d0, uint64_t d1, uint64_t d2,
                          uint64_t s1b, uint64_t s2b, uint32_t b0, uint32_t b1) {
    cuuint64_t dims[3] = {d0, d1, d2};
    cuuint64_t strides[2] = {s1b, s2b};
    cuuint32_t box[3] = {b0, b1, 1};
    cuuint32_t es[3] = {1, 1, 1};
    enc(m, CU_TENSOR_MAP_DATA_TYPE_BFLOAT16, 3, p, dims, strides, box, es,
        CU_TENSOR_MAP_INTERLEAVE_NONE, CU_TENSOR_MAP_SWIZZLE_128B,
        CU_TENSOR_MAP_L2_PROMOTION_L2_128B, CU_TENSOR_MAP_FLOAT_OOB_FILL_NONE);
}

extern "C" void kernel_launch(void* const* d_in, const int* in_sizes, int n_in,
                              void* d_out, int out_size) {
    const float* x    = (const float*)d_in[0];
    const float* W    = (const float*)d_in[1];
    const float* bias = (const float*)d_in[2];
    float* out        = (float*)d_out;

    void *pAh, *pAl, *pBh, *pBl;
    cudaGetSymbolAddress(&pAh, g_Ah);
    cudaGetSymbolAddress(&pAl, g_Al);
    cudaGetSymbolAddress(&pBh, g_Bh);
    cudaGetSymbolAddress(&pBl, g_Bl);

    void* fp = nullptr;
    cudaDriverEntryPointQueryResult qr;
    cudaGetDriverEntryPoint("cuTensorMapEncodeTiled", &fp, cudaEnableDefault, &qr);
    PFN_encodeTiled enc = (PFN_encodeTiled)fp;

    CUtensorMap mAh, mAl, mBh, mBl;
    make_map_bf16(enc, &mAh, pAh, K_TOT, M_TOT, 1,
                  (uint64_t)K_TOT * 2, (uint64_t)M_TOT * K_TOT * 2, KB, BM);
    make_map_bf16(enc, &mAl, pAl, K_TOT, M_TOT, 1,
                  (uint64_t)K_TOT * 2, (uint64_t)M_TOT * K_TOT * 2, KB, BM);
    make_map_bf16(enc, &mBh, pBh, K_TOT, N_TOT, D_TOT,
                  (uint64_t)K_TOT * 2, (uint64_t)N_TOT * K_TOT * 2, KB, BN);
    make_map_bf16(enc, &mBl, pBl, K_TOT, N_TOT, D_TOT,
                  (uint64_t)K_TOT * 2, (uint64_t)N_TOT * K_TOT * 2, KB, BN);

    split_x_kernel<<<(D_TOT * M_TOT * 512 / 4) / 256, 256>>>(
        x, (__nv_bfloat16*)pAh, (__nv_bfloat16*)pAl);
    split_w_kernel<<<dim3(2048 / 32, 512 / 32, 16), dim3(32, 8)>>>(
        W, (__nv_bfloat16*)pBh, (__nv_bfloat16*)pBl);

    int dev = 0, sms = 148;
    cudaGetDevice(&dev);
    cudaDeviceGetAttribute(&sms, cudaDevAttrMultiProcessorCount, dev);

    cudaFuncSetAttribute(tp_gemm_kernel, cudaFuncAttributeMaxDynamicSharedMemorySize,
                         SMEM_TOTAL);
    tp_gemm_kernel<<<sms, 192, SMEM_TOTAL>>>(mAh, mAl, mBh, mBl, bias, out, sms);
}